// round 4
// baseline (speedup 1.0000x reference)
#include <cuda_runtime.h>
#include <math.h>

#define HN   256
#define CINN 39
#define BN   128
#define SEQN 200
#define TN   1000
#define ON   61

// ---------------- scratch (device globals; no allocation allowed) ----------------
__device__ float g_Xp[2][SEQN][BN][HN];        // per-frame input projection + bi (NOT br)
__device__ float g_WrT[2][257][HN];            // WrT[d][i][h] = Wr_d[h][i]; row 256 = zeros
__device__ float g_block[SEQN][BN][2 * HN];    // 5-step block averages (merged fw|bw)
__device__ float g_y[SEQN][BN][ON];            // output-head pre/post scan values

// ---------------- 1) input projection: Xp[d][f][b][h] = (x[b,f]@Wi_d[h]) + bi ----------------
__global__ void __launch_bounds__(256) proj_kernel(
    const float* __restrict__ x,
    const float* __restrict__ Wi_fw, const float* __restrict__ bi_fw,
    const float* __restrict__ Wi_bw, const float* __restrict__ bi_bw)
{
    int blk = blockIdx.x;          // 0..399
    int d = blk & 1;
    int f = blk >> 1;
    const float* Wi = d ? Wi_bw : Wi_fw;
    const float* bi = d ? bi_bw : bi_fw;
    int h = threadIdx.x;

    __shared__ float xs[BN][CINN + 1];   // +1 pad
    for (int i = h; i < BN * CINN; i += blockDim.x) {
        int b = i / CINN, c = i % CINN;
        xs[b][c] = x[(b * SEQN + f) * CINN + c];
    }
    __syncthreads();

    float w[CINN];
#pragma unroll
    for (int c = 0; c < CINN; c++) w[c] = Wi[h * CINN + c];
    float bias = bi[h];

    for (int b = 0; b < BN; b += 4) {    // 4 independent FMA chains (ILP)
        float s0 = 0.0f, s1 = 0.0f, s2 = 0.0f, s3 = 0.0f;
#pragma unroll
        for (int c = 0; c < CINN; c++) {
            float wc = w[c];
            s0 = __fmaf_rn(xs[b + 0][c], wc, s0);
            s1 = __fmaf_rn(xs[b + 1][c], wc, s1);
            s2 = __fmaf_rn(xs[b + 2][c], wc, s2);
            s3 = __fmaf_rn(xs[b + 3][c], wc, s3);
        }
        g_Xp[d][f][b + 0][h] = __fadd_rn(s0, bias);
        g_Xp[d][f][b + 1][h] = __fadd_rn(s1, bias);
        g_Xp[d][f][b + 2][h] = __fadd_rn(s2, bias);
        g_Xp[d][f][b + 3][h] = __fadd_rn(s3, bias);
    }
}

// ---------------- 2) transpose Wr into column-major (+1 zero pad row) ----------------
__global__ void transpose_kernel(const float* __restrict__ Wr_fw, const float* __restrict__ Wr_bw)
{
    int idx = blockIdx.x * blockDim.x + threadIdx.x;
    int total = 2 * 257 * HN;
    if (idx >= total) return;
    int d = idx / (257 * HN);
    int r = idx % (257 * HN);
    int i = r / HN;
    int h = r % HN;
    const float* Wr = d ? Wr_bw : Wr_fw;
    g_WrT[d][i][h] = (i < HN) ? Wr[h * HN + i] : 0.0f;
}

// ---------------- 3) recurrence: 1 CTA = (direction, 2 batches); WrT rows 0..223 in SMEM ------
// smem layout (bytes):
//   [0, 230400)        Wsm: 225 rows x 256 floats (row 224 = zeros sentinel)
//   [230400, 230464)   smask: [2][8] uint
//   [230464, 231392)   slist_s: [2][232] ushort   (rows < 224)
//   [231392, 231552)   slist_g: [2][40] ushort    (rows 224..255; sentinel 256)
#define SMEM_RECUR 231552
#define WSM_ROWS   224

__global__ void __launch_bounds__(512) recur_kernel(
    const float* __restrict__ tau_m_fw, const float* __restrict__ tau_adp_fw,
    const float* __restrict__ tau_m_bw, const float* __restrict__ tau_adp_bw,
    const float* __restrict__ br_fw,   const float* __restrict__ br_bw)
{
    extern __shared__ char sm_raw[];
    float* Wsm = (float*)sm_raw;
    unsigned* smask = (unsigned*)(sm_raw + 230400);
    unsigned short* slist_s = (unsigned short*)(sm_raw + 230464);
    unsigned short* slist_g = (unsigned short*)(sm_raw + 231392);

    int d  = blockIdx.x & 1;
    int b0 = (blockIdx.x >> 1) * 2;     // 64 batch-pairs
    int tid = threadIdx.x;
    int g = tid >> 8;                    // 0/1 -> batch b0+g
    int h = tid & 255;
    int lane = tid & 31;

    // ---- stage WrT rows 0..223 into smem, row 224 = zeros ----
    const float4* W4 = (const float4*)&g_WrT[d][0][0];
    float4* Wsm4 = (float4*)Wsm;
    for (int idx = tid; idx < 225 * 64; idx += 512) {
        int row = idx >> 6;
        float4 v = (row < WSM_ROWS) ? __ldg(W4 + idx) : make_float4(0.f, 0.f, 0.f, 0.f);
        Wsm4[idx] = v;
    }

    const float* tm = d ? tau_m_bw : tau_m_fw;
    const float* ta = d ? tau_adp_bw : tau_adp_fw;
    const float* brp = d ? br_bw : br_fw;
    float alpha = (float)exp((double)__fdiv_rn(-1.0f, tm[h]));
    float ro    = (float)exp((double)__fdiv_rn(-1.0f, ta[h]));
    float oma   = __fsub_rn(1.0f, alpha);
    float omro  = __fsub_rn(1.0f, ro);
    float br    = brp[h];

    int b = b0 + g;
    float mem = 0.0f, spk = 0.0f, badp = 0.01f;
    float blocksum = 0.0f;
    float inp = 0.0f;
    __syncthreads();

    const float* WrTg = &g_WrT[d][0][0];

    for (int t = 0; t < TN; t++) {
        int tm5 = t % 5;
        bool reload = d ? (t == 0 || tm5 == 1) : (tm5 == 0);
        if (reload) {
            int f = d ? ((200 - (t + 4) / 5) % 200) : (t / 5);
            inp = g_Xp[d][f][b][h];
        }

        // ---- ballot: warp covers (g, h-word w = (h>>5)) ----
        unsigned m = __ballot_sync(0xffffffffu, spk != 0.0f);
        if (lane == 0) smask[g * 8 + (h >> 5)] = m;
        __syncthreads();   // S1: masks visible; also orders prior-step list reads before writes

        // every thread computes counts (broadcast smem reads)
        uint4 ma = *(const uint4*)(smask + g * 8);
        uint4 mb = *(const uint4*)(smask + g * 8 + 4);
        int c0 = __popc(ma.x), c1 = __popc(ma.y), c2 = __popc(ma.z), c3 = __popc(ma.w);
        int c4 = __popc(mb.x), c5 = __popc(mb.y), c6 = __popc(mb.z), c7 = __popc(mb.w);
        int cnt_s = c0 + c1 + c2 + c3 + c4 + c5 + c6;    // words 0..6 -> rows < 224
        int cnt_g = c7;                                   // word 7 -> rows 224..255
        int cnt_s_pad = (cnt_s + 7) & ~7;
        int cgp8 = (cnt_g + 7) & ~7; if (cgp8 < 8) cgp8 = 8;

        // builders: h<7 expand word h into slist_s; h==7 into slist_g
        if (h < 8) {
            unsigned wd[8] = {ma.x, ma.y, ma.z, ma.w, mb.x, mb.y, mb.z, mb.w};
            if (h < 7) {
                int base = 0;
#pragma unroll
                for (int j = 0; j < 7; j++) if (j < h) base += __popc(wd[j]);
                unsigned mm = wd[h];
                int p = base;
                while (mm) {
                    int bit = __ffs(mm) - 1;
                    slist_s[g * 232 + p] = (unsigned short)(h * 32 + bit);
                    p++; mm &= mm - 1;
                }
            } else {
                unsigned mm = wd[7];
                int p = 0;
                while (mm) {
                    int bit = __ffs(mm) - 1;
                    slist_g[g * 40 + p] = (unsigned short)(224 + bit);
                    p++; mm &= mm - 1;
                }
            }
        }
        // padders (disjoint slots from builders)
        if (h >= cnt_s && h < cnt_s_pad) slist_s[g * 232 + h] = (unsigned short)WSM_ROWS; // zero row
        if (h >= cnt_g && h < cgp8 && h < 40) slist_g[g * 40 + h] = (unsigned short)256;  // zero row
        __syncthreads();   // S2: lists visible

        // ---- issue first chunk of global-row loads early (rows 224..255, usually <=8) ----
        uint4 gu = *(const uint4*)(slist_g + g * 40);
        int gi0 = gu.x & 0xffff, gi1 = gu.x >> 16, gi2 = gu.y & 0xffff, gi3 = gu.y >> 16;
        int gi4 = gu.z & 0xffff, gi5 = gu.z >> 16, gi6 = gu.w & 0xffff, gi7 = gu.w >> 16;
        float gv0 = __ldg(WrTg + gi0 * HN + h);
        float gv1 = __ldg(WrTg + gi1 * HN + h);
        float gv2 = __ldg(WrTg + gi2 * HN + h);
        float gv3 = __ldg(WrTg + gi3 * HN + h);
        float gv4 = __ldg(WrTg + gi4 * HN + h);
        float gv5 = __ldg(WrTg + gi5 * HN + h);
        float gv6 = __ldg(WrTg + gi6 * HN + h);
        float gv7 = __ldg(WrTg + gi7 * HN + h);

        // ---- smem gather, ascending index (rows < 224) ----
        float rsum = 0.0f;
        for (int k = 0; k < cnt_s_pad; k += 8) {
            uint4 u = *(const uint4*)(slist_s + g * 232 + k);
            int i0 = u.x & 0xffff, i1 = u.x >> 16, i2 = u.y & 0xffff, i3 = u.y >> 16;
            int i4 = u.z & 0xffff, i5 = u.z >> 16, i6 = u.w & 0xffff, i7 = u.w >> 16;
            float v0 = Wsm[i0 * HN + h];
            float v1 = Wsm[i1 * HN + h];
            float v2 = Wsm[i2 * HN + h];
            float v3 = Wsm[i3 * HN + h];
            float v4 = Wsm[i4 * HN + h];
            float v5 = Wsm[i5 * HN + h];
            float v6 = Wsm[i6 * HN + h];
            float v7 = Wsm[i7 * HN + h];
            rsum = __fadd_rn(rsum, v0); rsum = __fadd_rn(rsum, v1);
            rsum = __fadd_rn(rsum, v2); rsum = __fadd_rn(rsum, v3);
            rsum = __fadd_rn(rsum, v4); rsum = __fadd_rn(rsum, v5);
            rsum = __fadd_rn(rsum, v6); rsum = __fadd_rn(rsum, v7);
        }
        // global rows ascend after smem rows -> overall ascending order preserved
        rsum = __fadd_rn(rsum, gv0); rsum = __fadd_rn(rsum, gv1);
        rsum = __fadd_rn(rsum, gv2); rsum = __fadd_rn(rsum, gv3);
        rsum = __fadd_rn(rsum, gv4); rsum = __fadd_rn(rsum, gv5);
        rsum = __fadd_rn(rsum, gv6); rsum = __fadd_rn(rsum, gv7);
        for (int k = 8; k < cgp8; k += 8) {   // rare overflow (>8 active in rows 224..255)
            uint4 u = *(const uint4*)(slist_g + g * 40 + k);
            int i0 = u.x & 0xffff, i1 = u.x >> 16, i2 = u.y & 0xffff, i3 = u.y >> 16;
            int i4 = u.z & 0xffff, i5 = u.z >> 16, i6 = u.w & 0xffff, i7 = u.w >> 16;
            float v0 = __ldg(WrTg + i0 * HN + h);
            float v1 = __ldg(WrTg + i1 * HN + h);
            float v2 = __ldg(WrTg + i2 * HN + h);
            float v3 = __ldg(WrTg + i3 * HN + h);
            float v4 = __ldg(WrTg + i4 * HN + h);
            float v5 = __ldg(WrTg + i5 * HN + h);
            float v6 = __ldg(WrTg + i6 * HN + h);
            float v7 = __ldg(WrTg + i7 * HN + h);
            rsum = __fadd_rn(rsum, v0); rsum = __fadd_rn(rsum, v1);
            rsum = __fadd_rn(rsum, v2); rsum = __fadd_rn(rsum, v3);
            rsum = __fadd_rn(rsum, v4); rsum = __fadd_rn(rsum, v5);
            rsum = __fadd_rn(rsum, v6); rsum = __fadd_rn(rsum, v7);
        }

        // ---- adaptive-LIF update; exact JAX association, NO FMA contraction ----
        float din = __fadd_rn(__fadd_rn(inp, rsum), br);
        badp = __fadd_rn(__fmul_rn(ro, badp), __fmul_rn(omro, spk));
        float Bth = __fadd_rn(0.01f, __fmul_rn(1.8f, badp));
        mem = __fsub_rn(__fadd_rn(__fmul_rn(mem, alpha), __fmul_rn(oma, din)),
                        __fmul_rn(Bth, spk));
        spk = (__fsub_rn(mem, Bth) > 0.0f) ? 1.0f : 0.0f;

        blocksum = __fadd_rn(blocksum, spk);
        if (tm5 == 4) {
            int s = d ? (199 - t / 5) : (t / 5);
            g_block[s][b][d * HN + h] = __fdiv_rn(blocksum, 5.0f);
            blocksum = 0.0f;
        }
    }
}

// ---------------- 4) output GEMM: y[s][b][o] = block[s][b]·W_out[o] + b_out[o] ----------------
// grid = 200 s * 8 btiles(16 batches); smem: W [61 rows x 516 fl stride] + x tile [16][512]
#define OW_STR4 129                       // float4 stride per W row (129*4 = 516 floats)
#define OUTMM_SMEM (61 * OW_STR4 * 16 + 16 * 128 * 16)
__global__ void __launch_bounds__(256) outmm_kernel(
    const float* __restrict__ W_out, const float* __restrict__ b_out)
{
    extern __shared__ char sm_raw[];
    float4* Wsm4 = (float4*)sm_raw;                     // [61][129]
    float4* xs4  = (float4*)(sm_raw + 61 * OW_STR4 * 16); // [16][128]

    int bt = blockIdx.x & 7;
    int s  = blockIdx.x >> 3;
    int tid = threadIdx.x;
    int o  = tid & 63;
    int bq = tid >> 6;      // 0..3 -> batches {bq, bq+4, bq+8, bq+12}

    const float4* W4 = (const float4*)W_out;
    for (int i = tid; i < ON * 128; i += 256) {
        int row = i >> 7, kq = i & 127;
        Wsm4[row * OW_STR4 + kq] = __ldg(W4 + row * 128 + kq);
    }
    const float4* gb4 = (const float4*)&g_block[s][bt * 16][0];
    for (int i = tid; i < 16 * 128; i += 256) xs4[i] = gb4[i];
    __syncthreads();

    int oe = (o < ON) ? o : (ON - 1);
    float a0 = 0.f, a1 = 0.f, a2 = 0.f, a3 = 0.f;
    const float4* wr = Wsm4 + oe * OW_STR4;
    const float4* x0 = xs4 + (bq + 0) * 128;
    const float4* x1 = xs4 + (bq + 4) * 128;
    const float4* x2 = xs4 + (bq + 8) * 128;
    const float4* x3 = xs4 + (bq + 12) * 128;
#pragma unroll 4
    for (int kq = 0; kq < 128; kq++) {
        float4 wv = wr[kq];
        float4 v0 = x0[kq], v1 = x1[kq], v2 = x2[kq], v3 = x3[kq];
        a0 = __fmaf_rn(v0.x, wv.x, a0); a0 = __fmaf_rn(v0.y, wv.y, a0);
        a0 = __fmaf_rn(v0.z, wv.z, a0); a0 = __fmaf_rn(v0.w, wv.w, a0);
        a1 = __fmaf_rn(v1.x, wv.x, a1); a1 = __fmaf_rn(v1.y, wv.y, a1);
        a1 = __fmaf_rn(v1.z, wv.z, a1); a1 = __fmaf_rn(v1.w, wv.w, a1);
        a2 = __fmaf_rn(v2.x, wv.x, a2); a2 = __fmaf_rn(v2.y, wv.y, a2);
        a2 = __fmaf_rn(v2.z, wv.z, a2); a2 = __fmaf_rn(v2.w, wv.w, a2);
        a3 = __fmaf_rn(v3.x, wv.x, a3); a3 = __fmaf_rn(v3.y, wv.y, a3);
        a3 = __fmaf_rn(v3.z, wv.z, a3); a3 = __fmaf_rn(v3.w, wv.w, a3);
    }
    if (o < ON) {
        float bo = b_out[o];
        int bb = bt * 16 + bq;
        g_y[s][bb + 0][o]  = __fadd_rn(a0, bo);
        g_y[s][bb + 4][o]  = __fadd_rn(a1, bo);
        g_y[s][bb + 8][o]  = __fadd_rn(a2, bo);
        g_y[s][bb + 12][o] = __fadd_rn(a3, bo);
    }
}

// ---------------- 5) leaky-integrator scan over s (per (b,o) chain) ----------------
__global__ void scan_kernel(const float* __restrict__ tau_m_out)
{
    int idx = blockIdx.x * blockDim.x + threadIdx.x;
    if (idx >= BN * ON) return;
    int b = idx / ON, o = idx % ON;
    float a = (float)exp((double)__fdiv_rn(-1.0f, tau_m_out[o]));
    float omA = __fsub_rn(1.0f, a);
    float mem = 0.0f;
    for (int s = 0; s < SEQN; s++) {
        mem = __fadd_rn(__fmul_rn(mem, a), __fmul_rn(omA, g_y[s][b][o]));
        g_y[s][b][o] = mem;
    }
}

// ---------------- 6) log_softmax per (s,b) row: one warp per row ----------------
__global__ void __launch_bounds__(256) softmax_kernel(float* __restrict__ out)
{
    int row = blockIdx.x * (blockDim.x >> 5) + (threadIdx.x >> 5);
    if (row >= SEQN * BN) return;
    int lane = threadIdx.x & 31;
    const float* yr = &g_y[0][0][0] + row * ON;

    float v0 = (lane < ON)      ? yr[lane]      : -1e30f;
    float v1 = (lane + 32 < ON) ? yr[lane + 32] : -1e30f;
    float mx = fmaxf(v0, v1);
#pragma unroll
    for (int off = 16; off; off >>= 1) mx = fmaxf(mx, __shfl_xor_sync(0xffffffffu, mx, off));
    float e = ((lane < ON) ? expf(__fsub_rn(v0, mx)) : 0.0f)
            + ((lane + 32 < ON) ? expf(__fsub_rn(v1, mx)) : 0.0f);
#pragma unroll
    for (int off = 16; off; off >>= 1) e += __shfl_xor_sync(0xffffffffu, e, off);
    float lse = __fadd_rn(mx, logf(e));
    if (lane < ON)      out[row * ON + lane]      = __fsub_rn(v0, lse);
    if (lane + 32 < ON) out[row * ON + lane + 32] = __fsub_rn(v1, lse);
}

// ---------------- host launcher ----------------
extern "C" void kernel_launch(void* const* d_in, const int* in_sizes, int n_in,
                              void* d_out, int out_size)
{
    const float* x         = (const float*)d_in[0];
    const float* Wi_fw     = (const float*)d_in[1];
    const float* bi_fw     = (const float*)d_in[2];
    const float* Wr_fw     = (const float*)d_in[3];
    const float* br_fw     = (const float*)d_in[4];
    const float* tau_m_fw  = (const float*)d_in[5];
    const float* tau_adp_fw= (const float*)d_in[6];
    const float* Wi_bw     = (const float*)d_in[7];
    const float* bi_bw     = (const float*)d_in[8];
    const float* Wr_bw     = (const float*)d_in[9];
    const float* br_bw     = (const float*)d_in[10];
    const float* tau_m_bw  = (const float*)d_in[11];
    const float* tau_adp_bw= (const float*)d_in[12];
    const float* W_out     = (const float*)d_in[13];
    const float* b_out     = (const float*)d_in[14];
    const float* tau_m_out = (const float*)d_in[15];

    static int configured = 0;
    if (!configured) {
        cudaFuncSetAttribute(recur_kernel, cudaFuncAttributeMaxDynamicSharedMemorySize, SMEM_RECUR);
        cudaFuncSetAttribute(outmm_kernel, cudaFuncAttributeMaxDynamicSharedMemorySize, OUTMM_SMEM);
        configured = 1;
    }

    proj_kernel<<<2 * SEQN, 256>>>(x, Wi_fw, bi_fw, Wi_bw, bi_bw);
    transpose_kernel<<<(2 * 257 * HN + 255) / 256, 256>>>(Wr_fw, Wr_bw);
    recur_kernel<<<128, 512, SMEM_RECUR>>>(tau_m_fw, tau_adp_fw, tau_m_bw, tau_adp_bw, br_fw, br_bw);
    outmm_kernel<<<SEQN * 8, 256, OUTMM_SMEM>>>(W_out, b_out);
    scan_kernel<<<(BN * ON + 255) / 256, 256>>>(tau_m_out);
    softmax_kernel<<<(SEQN * BN + 7) / 8, 256>>>((float*)d_out);
}

// round 5
// speedup vs baseline: 1.0957x; 1.0957x over previous
#include <cuda_runtime.h>
#include <math.h>

#define HN   256
#define CINN 39
#define BN   128
#define SEQN 200
#define TN   1000
#define ON   61

// ---------------- scratch (device globals; no allocation allowed) ----------------
__device__ float g_Xp[2][SEQN][BN][HN];        // per-frame input projection + bi (NOT br)
__device__ float g_WrT[2][257][HN];            // WrT[d][i][h] = Wr_d[h][i]; row 256 = zeros
__device__ float g_block[SEQN][BN][2 * HN];    // 5-step block averages (merged fw|bw)
__device__ float g_y[SEQN][BN][ON];            // output-head pre/post scan values

// ---------------- 1) input projection ----------------
__global__ void __launch_bounds__(256) proj_kernel(
    const float* __restrict__ x,
    const float* __restrict__ Wi_fw, const float* __restrict__ bi_fw,
    const float* __restrict__ Wi_bw, const float* __restrict__ bi_bw)
{
    int blk = blockIdx.x;          // 0..399
    int d = blk & 1;
    int f = blk >> 1;
    const float* Wi = d ? Wi_bw : Wi_fw;
    const float* bi = d ? bi_bw : bi_fw;
    int h = threadIdx.x;

    __shared__ float xs[BN][CINN + 1];
    for (int i = h; i < BN * CINN; i += blockDim.x) {
        int b = i / CINN, c = i % CINN;
        xs[b][c] = x[(b * SEQN + f) * CINN + c];
    }
    __syncthreads();

    float w[CINN];
#pragma unroll
    for (int c = 0; c < CINN; c++) w[c] = Wi[h * CINN + c];
    float bias = bi[h];

    for (int b = 0; b < BN; b += 4) {
        float s0 = 0.0f, s1 = 0.0f, s2 = 0.0f, s3 = 0.0f;
#pragma unroll
        for (int c = 0; c < CINN; c++) {
            float wc = w[c];
            s0 = __fmaf_rn(xs[b + 0][c], wc, s0);
            s1 = __fmaf_rn(xs[b + 1][c], wc, s1);
            s2 = __fmaf_rn(xs[b + 2][c], wc, s2);
            s3 = __fmaf_rn(xs[b + 3][c], wc, s3);
        }
        g_Xp[d][f][b + 0][h] = __fadd_rn(s0, bias);
        g_Xp[d][f][b + 1][h] = __fadd_rn(s1, bias);
        g_Xp[d][f][b + 2][h] = __fadd_rn(s2, bias);
        g_Xp[d][f][b + 3][h] = __fadd_rn(s3, bias);
    }
}

// ---------------- 2) transpose Wr (+1 zero pad row) ----------------
__global__ void transpose_kernel(const float* __restrict__ Wr_fw, const float* __restrict__ Wr_bw)
{
    int idx = blockIdx.x * blockDim.x + threadIdx.x;
    int total = 2 * 257 * HN;
    if (idx >= total) return;
    int d = idx / (257 * HN);
    int r = idx % (257 * HN);
    int i = r / HN;
    int h = r % HN;
    const float* Wr = d ? Wr_bw : Wr_fw;
    g_WrT[d][i][h] = (i < HN) ? Wr[h * HN + i] : 0.0f;
}

// ---------------- 3) recurrence: 1 CTA = (direction, 2 batches); per-group named barriers ----
// smem layout (bytes):
//   [0, 230400)        Wsm: 225 rows x 256 floats (row 224 = zeros sentinel)
//   [230400, 230464)   smask: [2][8] uint
//   [230464, 231392)   slist_s: [2][232] ushort   (rows < 224)
//   [231392, 231552)   slist_g: [2][40] ushort    (rows 224..255; sentinel 256)
#define SMEM_RECUR 231552
#define WSM_ROWS   224

__device__ __forceinline__ void group_bar(int id) {
    asm volatile("bar.sync %0, %1;" :: "r"(id), "r"(256) : "memory");
}

__global__ void __launch_bounds__(512) recur_kernel(
    const float* __restrict__ tau_m_fw, const float* __restrict__ tau_adp_fw,
    const float* __restrict__ tau_m_bw, const float* __restrict__ tau_adp_bw,
    const float* __restrict__ br_fw,   const float* __restrict__ br_bw)
{
    extern __shared__ char sm_raw[];
    float* Wsm = (float*)sm_raw;
    unsigned* smask = (unsigned*)(sm_raw + 230400);
    unsigned short* slist_s = (unsigned short*)(sm_raw + 230464);
    unsigned short* slist_g = (unsigned short*)(sm_raw + 231392);

    int d  = blockIdx.x & 1;
    int b0 = (blockIdx.x >> 1) * 2;
    int tid = threadIdx.x;
    int g = tid >> 8;                    // group: 0/1 -> independent chain (batch b0+g)
    int h = tid & 255;
    int lane = tid & 31;
    int barid = 1 + g;                   // named barrier per group

    // ---- stage WrT rows 0..223 into smem, row 224 = zeros ----
    const float4* W4 = (const float4*)&g_WrT[d][0][0];
    float4* Wsm4 = (float4*)Wsm;
    for (int idx = tid; idx < 225 * 64; idx += 512) {
        int row = idx >> 6;
        float4 v = (row < WSM_ROWS) ? __ldg(W4 + idx) : make_float4(0.f, 0.f, 0.f, 0.f);
        Wsm4[idx] = v;
    }

    const float* tm = d ? tau_m_bw : tau_m_fw;
    const float* ta = d ? tau_adp_bw : tau_adp_fw;
    const float* brp = d ? br_bw : br_fw;
    float alpha = (float)exp((double)__fdiv_rn(-1.0f, tm[h]));
    float ro    = (float)exp((double)__fdiv_rn(-1.0f, ta[h]));
    float oma   = __fsub_rn(1.0f, alpha);
    float omro  = __fsub_rn(1.0f, ro);
    float br    = brp[h];

    int b = b0 + g;
    float mem = 0.0f, spk = 0.0f, badp = 0.01f;
    float blocksum = 0.0f;
    float inp = 0.0f;
    __syncthreads();      // Wsm staged (block-wide, once)

    const float* WrTg = &g_WrT[d][0][0];

    for (int t = 0; t < TN; t++) {
        int tm5 = t % 5;
        bool reload = d ? (t == 0 || tm5 == 1) : (tm5 == 0);
        if (reload) {
            int f = d ? ((200 - (t + 4) / 5) % 200) : (t / 5);
            inp = g_Xp[d][f][b][h];
        }

        unsigned m = __ballot_sync(0xffffffffu, spk != 0.0f);
        if (lane == 0) smask[g * 8 + (h >> 5)] = m;
        group_bar(barid);   // S1: this group's masks visible (group-private data)

        uint4 ma = *(const uint4*)(smask + g * 8);
        uint4 mb = *(const uint4*)(smask + g * 8 + 4);
        int c0 = __popc(ma.x), c1 = __popc(ma.y), c2 = __popc(ma.z), c3 = __popc(ma.w);
        int c4 = __popc(mb.x), c5 = __popc(mb.y), c6 = __popc(mb.z), c7 = __popc(mb.w);
        int cnt_s = c0 + c1 + c2 + c3 + c4 + c5 + c6;
        int cnt_g = c7;
        int cnt_s_pad = (cnt_s + 7) & ~7;
        int cgp8 = (cnt_g + 7) & ~7; if (cgp8 < 8) cgp8 = 8;

        if (h < 8) {
            unsigned wd[8] = {ma.x, ma.y, ma.z, ma.w, mb.x, mb.y, mb.z, mb.w};
            if (h < 7) {
                int base = 0;
#pragma unroll
                for (int j = 0; j < 7; j++) if (j < h) base += __popc(wd[j]);
                unsigned mm = wd[h];
                int p = base;
                while (mm) {
                    int bit = __ffs(mm) - 1;
                    slist_s[g * 232 + p] = (unsigned short)(h * 32 + bit);
                    p++; mm &= mm - 1;
                }
            } else {
                unsigned mm = wd[7];
                int p = 0;
                while (mm) {
                    int bit = __ffs(mm) - 1;
                    slist_g[g * 40 + p] = (unsigned short)(224 + bit);
                    p++; mm &= mm - 1;
                }
            }
        }
        if (h >= cnt_s && h < cnt_s_pad) slist_s[g * 232 + h] = (unsigned short)WSM_ROWS;
        if (h >= cnt_g && h < cgp8 && h < 40) slist_g[g * 40 + h] = (unsigned short)256;
        group_bar(barid);   // S2: this group's lists visible

        // ---- early global loads (rows 224..255; sentinel row 256 = zeros) ----
        uint4 gu = *(const uint4*)(slist_g + g * 40);
        int gi0 = gu.x & 0xffff, gi1 = gu.x >> 16, gi2 = gu.y & 0xffff, gi3 = gu.y >> 16;
        int gi4 = gu.z & 0xffff, gi5 = gu.z >> 16, gi6 = gu.w & 0xffff, gi7 = gu.w >> 16;
        float gv0 = __ldg(WrTg + gi0 * HN + h);
        float gv1 = __ldg(WrTg + gi1 * HN + h);
        float gv2 = __ldg(WrTg + gi2 * HN + h);
        float gv3 = __ldg(WrTg + gi3 * HN + h);
        float gv4 = __ldg(WrTg + gi4 * HN + h);
        float gv5 = __ldg(WrTg + gi5 * HN + h);
        float gv6 = __ldg(WrTg + gi6 * HN + h);
        float gv7 = __ldg(WrTg + gi7 * HN + h);

        // ---- smem gather, ascending index (rows < 224) ----
        float rsum = 0.0f;
        for (int k = 0; k < cnt_s_pad; k += 8) {
            uint4 u = *(const uint4*)(slist_s + g * 232 + k);
            int i0 = u.x & 0xffff, i1 = u.x >> 16, i2 = u.y & 0xffff, i3 = u.y >> 16;
            int i4 = u.z & 0xffff, i5 = u.z >> 16, i6 = u.w & 0xffff, i7 = u.w >> 16;
            float v0 = Wsm[i0 * HN + h];
            float v1 = Wsm[i1 * HN + h];
            float v2 = Wsm[i2 * HN + h];
            float v3 = Wsm[i3 * HN + h];
            float v4 = Wsm[i4 * HN + h];
            float v5 = Wsm[i5 * HN + h];
            float v6 = Wsm[i6 * HN + h];
            float v7 = Wsm[i7 * HN + h];
            rsum = __fadd_rn(rsum, v0); rsum = __fadd_rn(rsum, v1);
            rsum = __fadd_rn(rsum, v2); rsum = __fadd_rn(rsum, v3);
            rsum = __fadd_rn(rsum, v4); rsum = __fadd_rn(rsum, v5);
            rsum = __fadd_rn(rsum, v6); rsum = __fadd_rn(rsum, v7);
        }
        rsum = __fadd_rn(rsum, gv0); rsum = __fadd_rn(rsum, gv1);
        rsum = __fadd_rn(rsum, gv2); rsum = __fadd_rn(rsum, gv3);
        rsum = __fadd_rn(rsum, gv4); rsum = __fadd_rn(rsum, gv5);
        rsum = __fadd_rn(rsum, gv6); rsum = __fadd_rn(rsum, gv7);
        for (int k = 8; k < cgp8; k += 8) {
            uint4 u = *(const uint4*)(slist_g + g * 40 + k);
            int i0 = u.x & 0xffff, i1 = u.x >> 16, i2 = u.y & 0xffff, i3 = u.y >> 16;
            int i4 = u.z & 0xffff, i5 = u.z >> 16, i6 = u.w & 0xffff, i7 = u.w >> 16;
            float v0 = __ldg(WrTg + i0 * HN + h);
            float v1 = __ldg(WrTg + i1 * HN + h);
            float v2 = __ldg(WrTg + i2 * HN + h);
            float v3 = __ldg(WrTg + i3 * HN + h);
            float v4 = __ldg(WrTg + i4 * HN + h);
            float v5 = __ldg(WrTg + i5 * HN + h);
            float v6 = __ldg(WrTg + i6 * HN + h);
            float v7 = __ldg(WrTg + i7 * HN + h);
            rsum = __fadd_rn(rsum, v0); rsum = __fadd_rn(rsum, v1);
            rsum = __fadd_rn(rsum, v2); rsum = __fadd_rn(rsum, v3);
            rsum = __fadd_rn(rsum, v4); rsum = __fadd_rn(rsum, v5);
            rsum = __fadd_rn(rsum, v6); rsum = __fadd_rn(rsum, v7);
        }

        // ---- adaptive-LIF update; exact JAX association, NO FMA contraction ----
        float din = __fadd_rn(__fadd_rn(inp, rsum), br);
        badp = __fadd_rn(__fmul_rn(ro, badp), __fmul_rn(omro, spk));
        float Bth = __fadd_rn(0.01f, __fmul_rn(1.8f, badp));
        mem = __fsub_rn(__fadd_rn(__fmul_rn(mem, alpha), __fmul_rn(oma, din)),
                        __fmul_rn(Bth, spk));
        spk = (__fsub_rn(mem, Bth) > 0.0f) ? 1.0f : 0.0f;

        blocksum = __fadd_rn(blocksum, spk);
        if (tm5 == 4) {
            int s = d ? (199 - t / 5) : (t / 5);
            g_block[s][b][d * HN + h] = __fdiv_rn(blocksum, 5.0f);
            blocksum = 0.0f;
        }
    }
}

// ---------------- 4) output GEMM; W stored k-major in smem (conflict-free LDS) ----------------
#define OW_K_STR 65                      // float4 stride per kq-row (pad 64->65)
#define OUTMM_SMEM ((128 * OW_K_STR + 16 * 128) * 16)
__global__ void __launch_bounds__(256) outmm_kernel(
    const float* __restrict__ W_out, const float* __restrict__ b_out)
{
    extern __shared__ char sm_raw[];
    float4* Wsm4 = (float4*)sm_raw;                          // [128][65] : [kq][o]
    float4* xs4  = (float4*)(sm_raw + 128 * OW_K_STR * 16);  // [16][128]

    int bt = blockIdx.x & 7;
    int s  = blockIdx.x >> 3;
    int tid = threadIdx.x;
    int o  = tid & 63;
    int bq = tid >> 6;      // 0..3 -> batches {bq, bq+4, bq+8, bq+12}

    const float4* W4 = (const float4*)W_out;
    for (int i = tid; i < ON * 128; i += 256) {      // coalesced LDG, k-major STS
        int oo = i >> 7, kq = i & 127;
        Wsm4[kq * OW_K_STR + oo] = __ldg(W4 + i);
    }
    for (int i = tid; i < 3 * 128; i += 256) {       // zero pad rows o=61..63
        int oo = 61 + (i >> 7), kq = i & 127;
        Wsm4[kq * OW_K_STR + oo] = make_float4(0.f, 0.f, 0.f, 0.f);
    }
    const float4* gb4 = (const float4*)&g_block[s][bt * 16][0];
    for (int i = tid; i < 16 * 128; i += 256) xs4[i] = gb4[i];
    __syncthreads();

    float a0 = 0.f, a1 = 0.f, a2 = 0.f, a3 = 0.f;
    const float4* x0 = xs4 + (bq + 0) * 128;
    const float4* x1 = xs4 + (bq + 4) * 128;
    const float4* x2 = xs4 + (bq + 8) * 128;
    const float4* x3 = xs4 + (bq + 12) * 128;
#pragma unroll 4
    for (int kq = 0; kq < 128; kq++) {
        float4 wv = Wsm4[kq * OW_K_STR + o];         // lanes: consecutive float4, 4 wf, no conflict
        float4 v0 = x0[kq], v1 = x1[kq], v2 = x2[kq], v3 = x3[kq];
        a0 = __fmaf_rn(v0.x, wv.x, a0); a0 = __fmaf_rn(v0.y, wv.y, a0);
        a0 = __fmaf_rn(v0.z, wv.z, a0); a0 = __fmaf_rn(v0.w, wv.w, a0);
        a1 = __fmaf_rn(v1.x, wv.x, a1); a1 = __fmaf_rn(v1.y, wv.y, a1);
        a1 = __fmaf_rn(v1.z, wv.z, a1); a1 = __fmaf_rn(v1.w, wv.w, a1);
        a2 = __fmaf_rn(v2.x, wv.x, a2); a2 = __fmaf_rn(v2.y, wv.y, a2);
        a2 = __fmaf_rn(v2.z, wv.z, a2); a2 = __fmaf_rn(v2.w, wv.w, a2);
        a3 = __fmaf_rn(v3.x, wv.x, a3); a3 = __fmaf_rn(v3.y, wv.y, a3);
        a3 = __fmaf_rn(v3.z, wv.z, a3); a3 = __fmaf_rn(v3.w, wv.w, a3);
    }
    if (o < ON) {
        float bo = b_out[o];
        int bb = bt * 16 + bq;
        g_y[s][bb + 0][o]  = __fadd_rn(a0, bo);
        g_y[s][bb + 4][o]  = __fadd_rn(a1, bo);
        g_y[s][bb + 8][o]  = __fadd_rn(a2, bo);
        g_y[s][bb + 12][o] = __fadd_rn(a3, bo);
    }
}

// ---------------- 5) leaky-integrator scan over s ----------------
__global__ void scan_kernel(const float* __restrict__ tau_m_out)
{
    int idx = blockIdx.x * blockDim.x + threadIdx.x;
    if (idx >= BN * ON) return;
    int b = idx / ON, o = idx % ON;
    float a = (float)exp((double)__fdiv_rn(-1.0f, tau_m_out[o]));
    float omA = __fsub_rn(1.0f, a);
    float mem = 0.0f;
    for (int s = 0; s < SEQN; s++) {
        mem = __fadd_rn(__fmul_rn(mem, a), __fmul_rn(omA, g_y[s][b][o]));
        g_y[s][b][o] = mem;
    }
}

// ---------------- 6) log_softmax per (s,b) row ----------------
__global__ void __launch_bounds__(256) softmax_kernel(float* __restrict__ out)
{
    int row = blockIdx.x * (blockDim.x >> 5) + (threadIdx.x >> 5);
    if (row >= SEQN * BN) return;
    int lane = threadIdx.x & 31;
    const float* yr = &g_y[0][0][0] + row * ON;

    float v0 = (lane < ON)      ? yr[lane]      : -1e30f;
    float v1 = (lane + 32 < ON) ? yr[lane + 32] : -1e30f;
    float mx = fmaxf(v0, v1);
#pragma unroll
    for (int off = 16; off; off >>= 1) mx = fmaxf(mx, __shfl_xor_sync(0xffffffffu, mx, off));
    float e = ((lane < ON) ? expf(__fsub_rn(v0, mx)) : 0.0f)
            + ((lane + 32 < ON) ? expf(__fsub_rn(v1, mx)) : 0.0f);
#pragma unroll
    for (int off = 16; off; off >>= 1) e += __shfl_xor_sync(0xffffffffu, e, off);
    float lse = __fadd_rn(mx, logf(e));
    if (lane < ON)      out[row * ON + lane]      = __fsub_rn(v0, lse);
    if (lane + 32 < ON) out[row * ON + lane + 32] = __fsub_rn(v1, lse);
}

// ---------------- host launcher ----------------
extern "C" void kernel_launch(void* const* d_in, const int* in_sizes, int n_in,
                              void* d_out, int out_size)
{
    const float* x         = (const float*)d_in[0];
    const float* Wi_fw     = (const float*)d_in[1];
    const float* bi_fw     = (const float*)d_in[2];
    const float* Wr_fw     = (const float*)d_in[3];
    const float* br_fw     = (const float*)d_in[4];
    const float* tau_m_fw  = (const float*)d_in[5];
    const float* tau_adp_fw= (const float*)d_in[6];
    const float* Wi_bw     = (const float*)d_in[7];
    const float* bi_bw     = (const float*)d_in[8];
    const float* Wr_bw     = (const float*)d_in[9];
    const float* br_bw     = (const float*)d_in[10];
    const float* tau_m_bw  = (const float*)d_in[11];
    const float* tau_adp_bw= (const float*)d_in[12];
    const float* W_out     = (const float*)d_in[13];
    const float* b_out     = (const float*)d_in[14];
    const float* tau_m_out = (const float*)d_in[15];

    static int configured = 0;
    if (!configured) {
        cudaFuncSetAttribute(recur_kernel, cudaFuncAttributeMaxDynamicSharedMemorySize, SMEM_RECUR);
        cudaFuncSetAttribute(outmm_kernel, cudaFuncAttributeMaxDynamicSharedMemorySize, OUTMM_SMEM);
        configured = 1;
    }

    proj_kernel<<<2 * SEQN, 256>>>(x, Wi_fw, bi_fw, Wi_bw, bi_bw);
    transpose_kernel<<<(2 * 257 * HN + 255) / 256, 256>>>(Wr_fw, Wr_bw);
    recur_kernel<<<128, 512, SMEM_RECUR>>>(tau_m_fw, tau_adp_fw, tau_m_bw, tau_adp_bw, br_fw, br_bw);
    outmm_kernel<<<SEQN * 8, 256, OUTMM_SMEM>>>(W_out, b_out);
    scan_kernel<<<(BN * ON + 255) / 256, 256>>>(tau_m_out);
    softmax_kernel<<<(SEQN * BN + 7) / 8, 256>>>((float*)d_out);
}